// round 9
// baseline (speedup 1.0000x reference)
#include <cuda_runtime.h>
#include <math.h>

#define TT    1024
#define BATCH 1024
#define HDIM  100
#define GDIM  400
#define BPB   8              // batch elems per block
#define NB1   (BATCH / BPB)  // 128 persistent blocks
#define NT1   400            // thread <-> (batch-pair bp in 0..3, j0 in 0..99)
#define NCH   8              // pipeline chunks
#define TCH   (TT / NCH)     // 128 timesteps per chunk

typedef unsigned long long u64;

__device__ float g_h1[(size_t)TT * BATCH * HDIM];    // layer-0 hidden states
__device__ float g_pre1[(size_t)TT * BATCH * GDIM];  // layer-1 gate pre-activations
__device__ float g_c0[BATCH * HDIM];                 // layer-0 cell state between chunks
__device__ float g_c1[BATCH * HDIM];                 // layer-1 cell state between chunks
__device__ float g_hs1[BATCH * HDIM];                // layer-1 hidden state between chunks

__device__ __forceinline__ float sigmf(float x) { return 1.0f / (1.0f + __expf(-x)); }
__device__ __forceinline__ float tanh_fast(float x) {
    float t = __expf(2.0f * x);
    return 1.0f - __fdividef(2.0f, t + 1.0f);
}
__device__ __forceinline__ u64 ffma2(u64 a, u64 b, u64 c) {
    u64 d;
    asm("fma.rn.f32x2 %0, %1, %2, %3;" : "=l"(d) : "l"(a), "l"(b), "l"(c));
    return d;
}
__device__ __forceinline__ float hsum2(u64 v) {
    float lo, hi;
    asm("mov.b64 {%0, %1}, %2;" : "=f"(lo), "=f"(hi) : "l"(v));
    return lo + hi;
}

// ============================================================================
// Layer-0 recurrence chunk [t0, t0+TCH). R5 structure: thread owns
// (batch-pair, j0), 8 gates, 2 in-register cells; one barrier/step.
// ============================================================================
__global__ void __launch_bounds__(NT1, 1) lstm_layer0_kernel(
    const float* __restrict__ x,      // [1024][3][1024]
    const float* __restrict__ Wih,    // [400][3]
    const float* __restrict__ Whh,    // [400][100]
    const float* __restrict__ bih,
    const float* __restrict__ bhh,
    int t0)
{
    extern __shared__ float sm[];
    float* sW    = sm;                   // 400*100
    float* sWin  = sW + GDIM * HDIM;     // 400*4
    float* sBias = sWin + GDIM * 4;      // 400
    float* sH0   = sBias + GDIM;         // 800
    float* sH1   = sH0 + BPB * HDIM;     // 800

    const int tid = threadIdx.x;
    const int bp  = tid & 3;
    const int j0  = tid >> 2;            // 0..99
    const int b0  = 2 * bp, b1 = b0 + 1;
    const int bg0 = blockIdx.x * BPB;

    for (int lin = tid; lin < GDIM * HDIM; lin += NT1) sW[lin] = Whh[lin];
    for (int lin = tid; lin < GDIM * 3; lin += NT1)
        sWin[(lin / 3) * 4 + (lin % 3)] = Wih[lin];
    for (int lin = tid; lin < GDIM; lin += NT1) sBias[lin] = bih[lin] + bhh[lin];
    // h carried via g_h1 (last step of previous chunk)
    for (int lin = tid; lin < BPB * HDIM; lin += NT1)
        sH0[lin] = (t0 == 0) ? 0.0f
                 : g_h1[((size_t)(t0 - 1) * BATCH + bg0) * HDIM + lin];
    __syncthreads();

    float bi[4], wi[4][3];
    #pragma unroll
    for (int g = 0; g < 4; g++) {
        bi[g] = sBias[g * HDIM + j0];
        wi[g][0] = sWin[(g * HDIM + j0) * 4 + 0];
        wi[g][1] = sWin[(g * HDIM + j0) * 4 + 1];
        wi[g][2] = sWin[(g * HDIM + j0) * 4 + 2];
    }
    const ulonglong2* wp0 = (const ulonglong2*)(sW + (0 * HDIM + j0) * HDIM);
    const ulonglong2* wp1 = (const ulonglong2*)(sW + (1 * HDIM + j0) * HDIM);
    const ulonglong2* wp2 = (const ulonglong2*)(sW + (2 * HDIM + j0) * HDIM);
    const ulonglong2* wp3 = (const ulonglong2*)(sW + (3 * HDIM + j0) * HDIM);
    const float* xa = x + (size_t)(bg0 + b0) * 3072;
    const float* xb = x + (size_t)(bg0 + b1) * 3072;

    float c0 = (t0 == 0) ? 0.0f : g_c0[(bg0 + b0) * HDIM + j0];
    float c1 = (t0 == 0) ? 0.0f : g_c0[(bg0 + b1) * HDIM + j0];
    float* sHr = sH0;
    float* sHw = sH1;

    for (int t = t0; t < t0 + TCH; t++) {
        float xa0 = xa[t], xa1 = xa[1024 + t], xa2 = xa[2048 + t];
        float xb0 = xb[t], xb1 = xb[1024 + t], xb2 = xb[2048 + t];

        u64 a00 = 0, a01 = 0, a02 = 0, a03 = 0;
        u64 a10 = 0, a11 = 0, a12 = 0, a13 = 0;
        const ulonglong2* hpa = (const ulonglong2*)(sHr + b0 * HDIM);
        const ulonglong2* hpb = (const ulonglong2*)(sHr + b1 * HDIM);
        #pragma unroll
        for (int k4 = 0; k4 < HDIM / 4; k4++) {
            ulonglong2 ha = hpa[k4];
            ulonglong2 hb = hpb[k4];
            ulonglong2 w;
            w = wp0[k4];
            a00 = ffma2(w.x, ha.x, a00); a00 = ffma2(w.y, ha.y, a00);
            a10 = ffma2(w.x, hb.x, a10); a10 = ffma2(w.y, hb.y, a10);
            w = wp1[k4];
            a01 = ffma2(w.x, ha.x, a01); a01 = ffma2(w.y, ha.y, a01);
            a11 = ffma2(w.x, hb.x, a11); a11 = ffma2(w.y, hb.y, a11);
            w = wp2[k4];
            a02 = ffma2(w.x, ha.x, a02); a02 = ffma2(w.y, ha.y, a02);
            a12 = ffma2(w.x, hb.x, a12); a12 = ffma2(w.y, hb.y, a12);
            w = wp3[k4];
            a03 = ffma2(w.x, ha.x, a03); a03 = ffma2(w.y, ha.y, a03);
            a13 = ffma2(w.x, hb.x, a13); a13 = ffma2(w.y, hb.y, a13);
        }

        float gi0 = hsum2(a00) + bi[0] + wi[0][0]*xa0 + wi[0][1]*xa1 + wi[0][2]*xa2;
        float gf0 = hsum2(a01) + bi[1] + wi[1][0]*xa0 + wi[1][1]*xa1 + wi[1][2]*xa2;
        float gg0 = hsum2(a02) + bi[2] + wi[2][0]*xa0 + wi[2][1]*xa1 + wi[2][2]*xa2;
        float go0 = hsum2(a03) + bi[3] + wi[3][0]*xa0 + wi[3][1]*xa1 + wi[3][2]*xa2;
        float gi1 = hsum2(a10) + bi[0] + wi[0][0]*xb0 + wi[0][1]*xb1 + wi[0][2]*xb2;
        float gf1 = hsum2(a11) + bi[1] + wi[1][0]*xb0 + wi[1][1]*xb1 + wi[1][2]*xb2;
        float gg1 = hsum2(a12) + bi[2] + wi[2][0]*xb0 + wi[2][1]*xb1 + wi[2][2]*xb2;
        float go1 = hsum2(a13) + bi[3] + wi[3][0]*xb0 + wi[3][1]*xb1 + wi[3][2]*xb2;

        c0 = sigmf(gf0) * c0 + sigmf(gi0) * tanh_fast(gg0);
        c1 = sigmf(gf1) * c1 + sigmf(gi1) * tanh_fast(gg1);
        float h0 = sigmf(go0) * tanh_fast(c0);
        float h1v = sigmf(go1) * tanh_fast(c1);

        sHw[b0 * HDIM + j0] = h0;
        sHw[b1 * HDIM + j0] = h1v;
        size_t rowbase = ((size_t)t * BATCH + bg0);
        g_h1[(rowbase + b0) * HDIM + j0] = h0;
        g_h1[(rowbase + b1) * HDIM + j0] = h1v;

        float* tmp = sHr; sHr = sHw; sHw = tmp;
        __syncthreads();
    }

    g_c0[(bg0 + b0) * HDIM + j0] = c0;
    g_c0[(bg0 + b1) * HDIM + j0] = c1;
}

// ============================================================================
// Layer-1 input GEMM chunk: pre1[r][j] = bias[j] + sum_k h1[r][k]*W_ih1[j][k]
// Small tile 64x50 (46.5 KB smem) so one block co-resides with an lstm block.
// ============================================================================
#define GA_MT 64
#define GA_NT 50
#define GA_TH 160            // 16 row-groups x 10 col-groups; thread tile 4x5
__global__ void __launch_bounds__(GA_TH, 4) gemm_ih1_kernel(
    const float* __restrict__ W,      // [400][100]
    const float* __restrict__ bih,
    const float* __restrict__ bhh,
    size_t row_off)                   // chunk base row
{
    extern __shared__ float sm[];
    float* sA = sm;                   // 64*102
    float* sB = sA + GA_MT * 102;     // 50*102

    const int tid = threadIdx.x;
    const size_t rbase = row_off + (size_t)blockIdx.y * GA_MT;
    const int cbase = blockIdx.x * GA_NT;

    for (int lin = tid; lin < GA_MT * HDIM; lin += GA_TH)
        sA[(lin / HDIM) * 102 + (lin % HDIM)] = g_h1[rbase * HDIM + lin];
    for (int lin = tid; lin < GA_NT * HDIM; lin += GA_TH)
        sB[(lin / HDIM) * 102 + (lin % HDIM)] = W[(size_t)cbase * HDIM + lin];
    __syncthreads();

    const int tx = tid % 10;   // 5 cols each
    const int ty = tid / 10;   // 4 rows each

    u64 acc[4][5];
    #pragma unroll
    for (int i = 0; i < 4; i++)
        #pragma unroll
        for (int u = 0; u < 5; u++) acc[i][u] = 0ULL;

    #pragma unroll 5
    for (int kp = 0; kp < HDIM / 2; kp++) {
        u64 b2[5];
        #pragma unroll
        for (int u = 0; u < 5; u++)
            b2[u] = *(const u64*)(sB + (tx * 5 + u) * 102 + 2 * kp);
        #pragma unroll
        for (int i = 0; i < 4; i++) {
            u64 a2 = *(const u64*)(sA + (ty * 4 + i) * 102 + 2 * kp);
            #pragma unroll
            for (int u = 0; u < 5; u++)
                acc[i][u] = ffma2(a2, b2[u], acc[i][u]);
        }
    }

    float bias[5];
    #pragma unroll
    for (int u = 0; u < 5; u++) {
        int col = cbase + tx * 5 + u;
        bias[u] = bih[col] + bhh[col];
    }
    #pragma unroll
    for (int i = 0; i < 4; i++) {
        size_t row = rbase + ty * 4 + i;
        #pragma unroll
        for (int u = 0; u < 5; u++)
            g_pre1[row * GDIM + cbase + tx * 5 + u] = hsum2(acc[i][u]) + bias[u];
    }
}

// ============================================================================
// Layer-1 recurrence chunk (+ fused FC on the last chunk).
// ============================================================================
__global__ void __launch_bounds__(NT1, 1) lstm_layer1_kernel(
    const float* __restrict__ Whh,    // [400][100]
    const float* __restrict__ fcw,    // [10][100]
    const float* __restrict__ fcb,    // [10]
    float* __restrict__ out,          // [1024][10]
    int t0)
{
    extern __shared__ float sm[];
    float* sW  = sm;                  // 400*100
    float* sH0 = sW + GDIM * HDIM;    // 800
    float* sH1 = sH0 + BPB * HDIM;    // 800

    const int tid = threadIdx.x;
    const int bp  = tid & 3;
    const int j0  = tid >> 2;
    const int b0  = 2 * bp, b1 = b0 + 1;
    const int bg0 = blockIdx.x * BPB;

    for (int lin = tid; lin < GDIM * HDIM; lin += NT1) sW[lin] = Whh[lin];
    for (int lin = tid; lin < BPB * HDIM; lin += NT1)
        sH0[lin] = (t0 == 0) ? 0.0f : g_hs1[bg0 * HDIM + lin];
    __syncthreads();

    const ulonglong2* wp0 = (const ulonglong2*)(sW + (0 * HDIM + j0) * HDIM);
    const ulonglong2* wp1 = (const ulonglong2*)(sW + (1 * HDIM + j0) * HDIM);
    const ulonglong2* wp2 = (const ulonglong2*)(sW + (2 * HDIM + j0) * HDIM);
    const ulonglong2* wp3 = (const ulonglong2*)(sW + (3 * HDIM + j0) * HDIM);

    float c0 = (t0 == 0) ? 0.0f : g_c1[(bg0 + b0) * HDIM + j0];
    float c1 = (t0 == 0) ? 0.0f : g_c1[(bg0 + b1) * HDIM + j0];
    float* sHr = sH0;
    float* sHw = sH1;

    for (int t = t0; t < t0 + TCH; t++) {
        const float* pra = g_pre1 + ((size_t)t * BATCH + bg0 + b0) * GDIM + j0;
        const float* prb = g_pre1 + ((size_t)t * BATCH + bg0 + b1) * GDIM + j0;
        float p00 = pra[0], p01 = pra[HDIM], p02 = pra[2 * HDIM], p03 = pra[3 * HDIM];
        float p10 = prb[0], p11 = prb[HDIM], p12 = prb[2 * HDIM], p13 = prb[3 * HDIM];

        u64 a00 = 0, a01 = 0, a02 = 0, a03 = 0;
        u64 a10 = 0, a11 = 0, a12 = 0, a13 = 0;
        const ulonglong2* hpa = (const ulonglong2*)(sHr + b0 * HDIM);
        const ulonglong2* hpb = (const ulonglong2*)(sHr + b1 * HDIM);
        #pragma unroll
        for (int k4 = 0; k4 < HDIM / 4; k4++) {
            ulonglong2 ha = hpa[k4];
            ulonglong2 hb = hpb[k4];
            ulonglong2 w;
            w = wp0[k4];
            a00 = ffma2(w.x, ha.x, a00); a00 = ffma2(w.y, ha.y, a00);
            a10 = ffma2(w.x, hb.x, a10); a10 = ffma2(w.y, hb.y, a10);
            w = wp1[k4];
            a01 = ffma2(w.x, ha.x, a01); a01 = ffma2(w.y, ha.y, a01);
            a11 = ffma2(w.x, hb.x, a11); a11 = ffma2(w.y, hb.y, a11);
            w = wp2[k4];
            a02 = ffma2(w.x, ha.x, a02); a02 = ffma2(w.y, ha.y, a02);
            a12 = ffma2(w.x, hb.x, a12); a12 = ffma2(w.y, hb.y, a12);
            w = wp3[k4];
            a03 = ffma2(w.x, ha.x, a03); a03 = ffma2(w.y, ha.y, a03);
            a13 = ffma2(w.x, hb.x, a13); a13 = ffma2(w.y, hb.y, a13);
        }

        float gi0 = hsum2(a00) + p00, gf0 = hsum2(a01) + p01;
        float gg0 = hsum2(a02) + p02, go0 = hsum2(a03) + p03;
        float gi1 = hsum2(a10) + p10, gf1 = hsum2(a11) + p11;
        float gg1 = hsum2(a12) + p12, go1 = hsum2(a13) + p13;

        c0 = sigmf(gf0) * c0 + sigmf(gi0) * tanh_fast(gg0);
        c1 = sigmf(gf1) * c1 + sigmf(gi1) * tanh_fast(gg1);
        sHw[b0 * HDIM + j0] = sigmf(go0) * tanh_fast(c0);
        sHw[b1 * HDIM + j0] = sigmf(go1) * tanh_fast(c1);

        float* tmp = sHr; sHr = sHw; sHw = tmp;
        __syncthreads();
    }

    g_c1[(bg0 + b0) * HDIM + j0] = c0;
    g_c1[(bg0 + b1) * HDIM + j0] = c1;
    for (int lin = tid; lin < BPB * HDIM; lin += NT1)
        g_hs1[bg0 * HDIM + lin] = sHr[lin];

    if (t0 + TCH == TT && tid < BPB * 10) {
        int bb = tid / 10, o = tid % 10;
        float acc = fcb[o];
        const float* wrow = fcw + o * HDIM;
        const float* hrow = sHr + bb * HDIM;
        #pragma unroll 4
        for (int k = 0; k < HDIM; k++) acc = fmaf(wrow[k], hrow[k], acc);
        out[(bg0 + bb) * 10 + o] = acc;
    }
}

// ============================================================================
// launch: chunked pipeline with a forked side stream for the GEMM so it
// overlaps (co-resides) with the recurrent kernels.
// ============================================================================
extern "C" void kernel_launch(void* const* d_in, const int* in_sizes, int n_in,
                              void* d_out, int out_size)
{
    (void)in_sizes; (void)n_in; (void)out_size;
    const float* x    = (const float*)d_in[0];
    const float* Wih0 = (const float*)d_in[1];
    const float* Whh0 = (const float*)d_in[2];
    const float* bih0 = (const float*)d_in[3];
    const float* bhh0 = (const float*)d_in[4];
    const float* Wih1 = (const float*)d_in[5];
    const float* Whh1 = (const float*)d_in[6];
    const float* bih1 = (const float*)d_in[7];
    const float* bhh1 = (const float*)d_in[8];
    const float* fcw  = (const float*)d_in[9];
    const float* fcb  = (const float*)d_in[10];
    float* out = (float*)d_out;

    const size_t smem0 = (size_t)(GDIM * HDIM + GDIM * 4 + GDIM + 2 * BPB * HDIM) * 4;
    const size_t smemA = (size_t)(GA_MT * 102 + GA_NT * 102) * 4;
    const size_t smem1 = (size_t)(GDIM * HDIM + 2 * BPB * HDIM) * 4;

    cudaFuncSetAttribute(lstm_layer0_kernel, cudaFuncAttributeMaxDynamicSharedMemorySize, (int)smem0);
    cudaFuncSetAttribute(gemm_ih1_kernel,    cudaFuncAttributeMaxDynamicSharedMemorySize, (int)smemA);
    cudaFuncSetAttribute(lstm_layer1_kernel, cudaFuncAttributeMaxDynamicSharedMemorySize, (int)smem1);

    // Side stream + events (created fresh each call; kernel_launch only runs
    // a handful of times — correctness pass + capture — so no meaningful leak).
    cudaStream_t s1;
    cudaStreamCreateWithFlags(&s1, cudaStreamNonBlocking);
    cudaEvent_t evL[NCH], evG[NCH];
    for (int i = 0; i < NCH; i++) {
        cudaEventCreateWithFlags(&evL[i], cudaEventDisableTiming);
        cudaEventCreateWithFlags(&evG[i], cudaEventDisableTiming);
    }

    dim3 ggrid(GDIM / GA_NT, (TCH * BATCH) / GA_MT);   // (8, 2048) per chunk

    for (int i = 0; i < NCH; i++) {
        lstm_layer0_kernel<<<NB1, NT1, smem0>>>(x, Wih0, Whh0, bih0, bhh0, i * TCH);
        cudaEventRecord(evL[i], 0);
        cudaStreamWaitEvent(s1, evL[i], 0);
        gemm_ih1_kernel<<<ggrid, GA_TH, smemA, s1>>>(Wih1, bih1, bhh1,
                                                     (size_t)i * TCH * BATCH);
        cudaEventRecord(evG[i], s1);
    }
    for (int i = 0; i < NCH; i++) {
        cudaStreamWaitEvent(0, evG[i], 0);   // pre1 chunk i ready
        lstm_layer1_kernel<<<NB1, NT1, smem1>>>(Whh1, fcw, fcb, out, i * TCH);
    }
}